// round 2
// baseline (speedup 1.0000x reference)
#include <cuda_runtime.h>
#include <cuda_bf16.h>
#include <mma.h>

using namespace nvcuda;

// Problem dims (fixed by the dataset)
#define NPTS 8192
#define DDIM 512
#define ODIM 512

static constexpr float INV2SIG2 = 1.0f / 2048.0f;   // 1/(2*32*32)
static constexpr float EPSV = 1e-8f;

// ---------------- scratch (static __device__ globals; no allocation) ----------------
__device__ __nv_bfloat16 g_xhi[NPTS * DDIM];
__device__ __nv_bfloat16 g_xlo[NPTS * DDIM];
__device__ __nv_bfloat16 g_Whi[ODIM * DDIM];
__device__ __nv_bfloat16 g_Wlo[ODIM * DDIM];
__device__ float g_sq[NPTS];
__device__ float g_invr[NPTS];
__device__ __nv_bfloat16 g_Phi[(size_t)NPTS * NPTS];   // 128 MB
__device__ __nv_bfloat16 g_Plo[(size_t)NPTS * NPTS];   // 128 MB
__device__ float g_O[(size_t)NPTS * DDIM];             // 16 MB

// ---------------- K1a: row squared norms + hi/lo split of x ----------------
__global__ void k_prep_x(const float* __restrict__ x) {
    int row = blockIdx.x * 8 + (threadIdx.x >> 5);
    int lane = threadIdx.x & 31;
    const float* xr = x + (size_t)row * DDIM;
    float s = 0.f;
    for (int c = lane; c < DDIM; c += 32) {
        float v = xr[c];
        s += v * v;
        __nv_bfloat16 hi = __float2bfloat16(v);
        g_xhi[(size_t)row * DDIM + c] = hi;
        g_xlo[(size_t)row * DDIM + c] = __float2bfloat16(v - __bfloat162float(hi));
    }
    #pragma unroll
    for (int o = 16; o > 0; o >>= 1) s += __shfl_xor_sync(0xffffffff, s, o);
    if (lane == 0) g_sq[row] = s;
}

// ---------------- K1b: hi/lo split of W ----------------
__global__ void k_prep_w(const float* __restrict__ W) {
    int i = blockIdx.x * blockDim.x + threadIdx.x;
    if (i < ODIM * DDIM) {
        float v = W[i];
        __nv_bfloat16 hi = __float2bfloat16(v);
        g_Whi[i] = hi;
        g_Wlo[i] = __float2bfloat16(v - __bfloat162float(hi));
    }
}

// ---------------- K2: Gram tile -> exp epilogue -> P (hi/lo) ----------------
// 128x128 tile, K=512, bf16 wmma (x_hi only; error budget allows it).
// 256 threads = 8 warps, warp grid 4(M) x 2(N), warp tile 32x64.
__global__ void k_gauss() {
    __shared__ __nv_bfloat16 As[128][40];
    __shared__ __nv_bfloat16 Bs[128][40];
    __shared__ float sqi[128], sqj[128];
    __shared__ float patch[8][16][20];

    int i0 = blockIdx.y * 128;
    int j0 = blockIdx.x * 128;
    int tid = threadIdx.x;
    int warp = tid >> 5, lane = tid & 31;
    int wm = warp >> 1;   // 0..3
    int wn = warp & 1;    // 0..1

    if (tid < 128) sqi[tid] = g_sq[i0 + tid];
    else           sqj[tid - 128] = g_sq[j0 + tid - 128];

    wmma::fragment<wmma::accumulator, 16, 16, 16, float> acc[2][4];
    #pragma unroll
    for (int a = 0; a < 2; a++)
        #pragma unroll
        for (int b = 0; b < 4; b++) wmma::fill_fragment(acc[a][b], 0.f);

    for (int kt = 0; kt < DDIM; kt += 32) {
        for (int idx = tid; idx < 128 * 32; idx += 256) {
            int r = idx >> 5, c = idx & 31;
            As[r][c] = g_xhi[(size_t)(i0 + r) * DDIM + kt + c];
            Bs[r][c] = g_xhi[(size_t)(j0 + r) * DDIM + kt + c];
        }
        __syncthreads();
        #pragma unroll
        for (int kc = 0; kc < 2; kc++) {
            wmma::fragment<wmma::matrix_a, 16, 16, 16, __nv_bfloat16, wmma::row_major> af[2];
            wmma::fragment<wmma::matrix_b, 16, 16, 16, __nv_bfloat16, wmma::col_major> bf[4];
            #pragma unroll
            for (int mi = 0; mi < 2; mi++)
                wmma::load_matrix_sync(af[mi], &As[wm * 32 + mi * 16][kc * 16], 40);
            #pragma unroll
            for (int ni = 0; ni < 4; ni++)
                wmma::load_matrix_sync(bf[ni], &Bs[wn * 64 + ni * 16][kc * 16], 40);
            #pragma unroll
            for (int mi = 0; mi < 2; mi++)
                #pragma unroll
                for (int ni = 0; ni < 4; ni++)
                    wmma::mma_sync(acc[mi][ni], af[mi], bf[ni], acc[mi][ni]);
        }
        __syncthreads();
    }

    // epilogue: sqd -> exp -> split -> store P
    #pragma unroll
    for (int mi = 0; mi < 2; mi++) {
        #pragma unroll
        for (int ni = 0; ni < 4; ni++) {
            wmma::store_matrix_sync(&patch[warp][0][0], acc[mi][ni], 20, wmma::mem_row_major);
            __syncwarp();
            int rr = lane >> 1;
            int cc0 = (lane & 1) * 8;
            int gi = i0 + wm * 32 + mi * 16 + rr;
            int jbase = wn * 64 + ni * 16 + cc0;
            float si = sqi[wm * 32 + mi * 16 + rr];
            #pragma unroll
            for (int e = 0; e < 8; e++) {
                float g = patch[warp][rr][cc0 + e];
                float sqd = fmaxf(si + sqj[jbase + e] - 2.f * g, 0.f);
                float p = __expf(-sqd * INV2SIG2);
                __nv_bfloat16 hi = __float2bfloat16(p);
                size_t o = (size_t)gi * NPTS + (j0 + jbase + e);
                g_Phi[o] = hi;
                g_Plo[o] = __float2bfloat16(p - __bfloat162float(hi));
            }
            __syncwarp();
        }
    }
}

// ---------------- K2.5: deterministic row sums -> 1/(r+eps) ----------------
__global__ void k_rowsum() {
    int row = blockIdx.x;
    size_t base = (size_t)row * NPTS;
    float s = 0.f;
    for (int c = threadIdx.x; c < NPTS; c += 256)
        s += __bfloat162float(g_Phi[base + c]) + __bfloat162float(g_Plo[base + c]);
    __shared__ float red[256];
    red[threadIdx.x] = s;
    __syncthreads();
    for (int o = 128; o > 0; o >>= 1) {
        if (threadIdx.x < o) red[threadIdx.x] += red[threadIdx.x + o];
        __syncthreads();
    }
    if (threadIdx.x == 0) g_invr[row] = 1.f / (red[0] + EPSV);
}

// ---------------- K3: O = P @ x with hi/lo split (3 products) ----------------
// BM=64, BN=128, BK=32, K=8192. 8 warps 2(M) x 4(N), warp tile 32x32.
__global__ void k_pv() {
    __shared__ __nv_bfloat16 Ah[64][40], Al[64][40];
    __shared__ __nv_bfloat16 Bh[32][136], Bl[32][136];

    int i0 = blockIdx.y * 64;
    int n0 = blockIdx.x * 128;
    int tid = threadIdx.x, warp = tid >> 5;
    int wm = warp >> 2;  // 0..1
    int wn = warp & 3;   // 0..3

    wmma::fragment<wmma::accumulator, 16, 16, 16, float> acc[2][2];
    #pragma unroll
    for (int a = 0; a < 2; a++)
        #pragma unroll
        for (int b = 0; b < 2; b++) wmma::fill_fragment(acc[a][b], 0.f);

    for (int kt = 0; kt < NPTS; kt += 32) {
        for (int idx = tid; idx < 64 * 32; idx += 256) {
            int r = idx >> 5, c = idx & 31;
            size_t o = (size_t)(i0 + r) * NPTS + kt + c;
            Ah[r][c] = g_Phi[o];
            Al[r][c] = g_Plo[o];
        }
        for (int idx = tid; idx < 32 * 128; idx += 256) {
            int r = idx >> 7, c = idx & 127;
            size_t o = (size_t)(kt + r) * DDIM + n0 + c;
            Bh[r][c] = g_xhi[o];
            Bl[r][c] = g_xlo[o];
        }
        __syncthreads();
        #pragma unroll
        for (int kc = 0; kc < 2; kc++) {
            wmma::fragment<wmma::matrix_a, 16, 16, 16, __nv_bfloat16, wmma::row_major> ah[2], al[2];
            wmma::fragment<wmma::matrix_b, 16, 16, 16, __nv_bfloat16, wmma::row_major> bh[2], bl[2];
            #pragma unroll
            for (int mi = 0; mi < 2; mi++) {
                wmma::load_matrix_sync(ah[mi], &Ah[wm * 32 + mi * 16][kc * 16], 40);
                wmma::load_matrix_sync(al[mi], &Al[wm * 32 + mi * 16][kc * 16], 40);
            }
            #pragma unroll
            for (int ni = 0; ni < 2; ni++) {
                wmma::load_matrix_sync(bh[ni], &Bh[kc * 16][wn * 32 + ni * 16], 136);
                wmma::load_matrix_sync(bl[ni], &Bl[kc * 16][wn * 32 + ni * 16], 136);
            }
            #pragma unroll
            for (int mi = 0; mi < 2; mi++)
                #pragma unroll
                for (int ni = 0; ni < 2; ni++) {
                    wmma::mma_sync(acc[mi][ni], ah[mi], bh[ni], acc[mi][ni]);
                    wmma::mma_sync(acc[mi][ni], ah[mi], bl[ni], acc[mi][ni]);
                    wmma::mma_sync(acc[mi][ni], al[mi], bh[ni], acc[mi][ni]);
                }
        }
        __syncthreads();
    }
    #pragma unroll
    for (int mi = 0; mi < 2; mi++)
        #pragma unroll
        for (int ni = 0; ni < 2; ni++)
            wmma::store_matrix_sync(
                &g_O[(size_t)(i0 + wm * 32 + mi * 16) * DDIM + n0 + wn * 32 + ni * 16],
                acc[mi][ni], DDIM, wmma::mem_row_major);
}

// ---------------- K4: out = (O * invr) @ W^T + b, hi/lo split ----------------
// BM=64, BN=128, BK=32, K=512. Same warp layout as K3. B is col-major (W rows).
__global__ void k_head(const float* __restrict__ bvec, float* __restrict__ out) {
    __shared__ __nv_bfloat16 Ah[64][40], Al[64][40];
    __shared__ __nv_bfloat16 Bh[128][40], Bl[128][40];
    __shared__ float patch[8][16][20];
    __shared__ float bs[128];

    int i0 = blockIdx.y * 64;
    int n0 = blockIdx.x * 128;
    int tid = threadIdx.x, warp = tid >> 5, lane = tid & 31;
    int wm = warp >> 2;  // 0..1
    int wn = warp & 3;   // 0..3

    if (tid < 128) bs[tid] = bvec[n0 + tid];

    wmma::fragment<wmma::accumulator, 16, 16, 16, float> acc[2][2];
    #pragma unroll
    for (int a = 0; a < 2; a++)
        #pragma unroll
        for (int b = 0; b < 2; b++) wmma::fill_fragment(acc[a][b], 0.f);

    for (int kt = 0; kt < DDIM; kt += 32) {
        for (int idx = tid; idx < 64 * 32; idx += 256) {
            int r = idx >> 5, c = idx & 31;
            float v = g_O[(size_t)(i0 + r) * DDIM + kt + c] * g_invr[i0 + r];
            __nv_bfloat16 hi = __float2bfloat16(v);
            Ah[r][c] = hi;
            Al[r][c] = __float2bfloat16(v - __bfloat162float(hi));
        }
        for (int idx = tid; idx < 128 * 32; idx += 256) {
            int r = idx >> 5, c = idx & 31;
            size_t o = (size_t)(n0 + r) * DDIM + kt + c;
            Bh[r][c] = g_Whi[o];
            Bl[r][c] = g_Wlo[o];
        }
        __syncthreads();
        #pragma unroll
        for (int kc = 0; kc < 2; kc++) {
            wmma::fragment<wmma::matrix_a, 16, 16, 16, __nv_bfloat16, wmma::row_major> ah[2], al[2];
            wmma::fragment<wmma::matrix_b, 16, 16, 16, __nv_bfloat16, wmma::col_major> bh[2], bl[2];
            #pragma unroll
            for (int mi = 0; mi < 2; mi++) {
                wmma::load_matrix_sync(ah[mi], &Ah[wm * 32 + mi * 16][kc * 16], 40);
                wmma::load_matrix_sync(al[mi], &Al[wm * 32 + mi * 16][kc * 16], 40);
            }
            #pragma unroll
            for (int ni = 0; ni < 2; ni++) {
                wmma::load_matrix_sync(bh[ni], &Bh[wn * 32 + ni * 16][kc * 16], 40);
                wmma::load_matrix_sync(bl[ni], &Bl[wn * 32 + ni * 16][kc * 16], 40);
            }
            #pragma unroll
            for (int mi = 0; mi < 2; mi++)
                #pragma unroll
                for (int ni = 0; ni < 2; ni++) {
                    wmma::mma_sync(acc[mi][ni], ah[mi], bh[ni], acc[mi][ni]);
                    wmma::mma_sync(acc[mi][ni], ah[mi], bl[ni], acc[mi][ni]);
                    wmma::mma_sync(acc[mi][ni], al[mi], bh[ni], acc[mi][ni]);
                }
        }
        __syncthreads();
    }

    #pragma unroll
    for (int mi = 0; mi < 2; mi++) {
        #pragma unroll
        for (int ni = 0; ni < 2; ni++) {
            wmma::store_matrix_sync(&patch[warp][0][0], acc[mi][ni], 20, wmma::mem_row_major);
            __syncwarp();
            int rr = lane >> 1;
            int cc0 = (lane & 1) * 8;
            int gi = i0 + wm * 32 + mi * 16 + rr;
            int nb = wn * 32 + ni * 16 + cc0;
            #pragma unroll
            for (int e = 0; e < 8; e++)
                out[(size_t)gi * ODIM + n0 + nb + e] = patch[warp][rr][cc0 + e] + bs[nb + e];
            __syncwarp();
        }
    }
}

// ---------------- launch ----------------
extern "C" void kernel_launch(void* const* d_in, const int* in_sizes, int n_in,
                              void* d_out, int out_size) {
    const float* x = (const float*)d_in[0];
    const float* W = (const float*)d_in[1];
    const float* b = (const float*)d_in[2];
    float* out = (float*)d_out;

    k_prep_x<<<NPTS / 8, 256>>>(x);
    k_prep_w<<<(ODIM * DDIM + 255) / 256, 256>>>(W);
    k_gauss<<<dim3(NPTS / 128, NPTS / 128), 256>>>();
    k_rowsum<<<NPTS, 256>>>();
    k_pv<<<dim3(DDIM / 128, NPTS / 64), 256>>>();
    k_head<<<dim3(ODIM / 128, NPTS / 64), 256>>>(b, out);
}

// round 4
// speedup vs baseline: 6.0572x; 6.0572x over previous
#include <cuda_runtime.h>
#include <cuda_fp16.h>
#include <mma.h>
#include <cstdint>

using namespace nvcuda;

#define NPTS 8192
#define DDIM 512
#define ODIM 512

static constexpr float INV2SIG2 = 1.0f / 2048.0f;   // 1/(2*32*32)
static constexpr float EPSV = 1e-8f;

// ---------------- scratch ----------------
__device__ __half g_x[(size_t)NPTS * DDIM];          // 8 MB
__device__ __half g_W[(size_t)ODIM * DDIM];          // 0.5 MB
__device__ __half g_P[(size_t)NPTS * NPTS];          // 128 MB
__device__ float  g_sq[NPTS];
__device__ float  g_invr[NPTS];
__device__ float  g_O[(size_t)NPTS * DDIM];          // 16 MB

// ---------------- cp.async helpers ----------------
__device__ __forceinline__ void cp16(void* dst_smem, const void* src) {
    unsigned int d = (unsigned int)__cvta_generic_to_shared(dst_smem);
    asm volatile("cp.async.cg.shared.global [%0], [%1], 16;" :: "r"(d), "l"(src));
}
#define CP_COMMIT() asm volatile("cp.async.commit_group;" ::: "memory")
#define CP_WAIT1()  asm volatile("cp.async.wait_group 1;" ::: "memory")
#define CP_WAIT0()  asm volatile("cp.async.wait_group 0;" ::: "memory")

// ---------------- K1a: fp16 convert of x + row squared norms ----------------
__global__ void k_prep_x(const float* __restrict__ x) {
    int row = blockIdx.x * 8 + (threadIdx.x >> 5);
    int lane = threadIdx.x & 31;
    const float4* xr = (const float4*)(x + (size_t)row * DDIM);
    float s = 0.f;
    #pragma unroll
    for (int i = lane; i < 128; i += 32) {
        float4 v = xr[i];
        s += v.x * v.x + v.y * v.y + v.z * v.z + v.w * v.w;
        __half2* dst = (__half2*)(g_x + (size_t)row * DDIM + i * 4);
        dst[0] = __floats2half2_rn(v.x, v.y);
        dst[1] = __floats2half2_rn(v.z, v.w);
    }
    #pragma unroll
    for (int o = 16; o > 0; o >>= 1) s += __shfl_xor_sync(0xffffffff, s, o);
    if (lane == 0) g_sq[row] = s;
}

// ---------------- K1b: fp16 convert of W ----------------
__global__ void k_prep_w(const float* __restrict__ W) {
    int i = blockIdx.x * blockDim.x + threadIdx.x;   // over float4s (65536)
    float4 v = ((const float4*)W)[i];
    __half2* dst = (__half2*)(g_W + (size_t)i * 4);
    dst[0] = __floats2half2_rn(v.x, v.y);
    dst[1] = __floats2half2_rn(v.z, v.w);
}

// ---------------- K2: Gram 128x128 tile -> exp -> P (fp16) ----------------
// 256 threads, 8 warps 4(M) x 2(N), warp tile 32x64, K=512, BK=32, double-buffered.
__global__ void __launch_bounds__(256) k_gauss() {
    __shared__ __half As[2][128][40];
    __shared__ __half Bs[2][128][40];
    __shared__ float sqj[128];

    int i0 = blockIdx.y * 128;
    int j0 = blockIdx.x * 128;
    int tid = threadIdx.x, warp = tid >> 5, lane = tid & 31;
    int wm = warp >> 1;   // 0..3
    int wn = warp & 1;    // 0..1

    if (tid < 128) sqj[tid] = g_sq[j0 + tid];

    wmma::fragment<wmma::accumulator, 16, 16, 16, float> acc[2][4];
    #pragma unroll
    for (int a = 0; a < 2; a++)
        #pragma unroll
        for (int b = 0; b < 4; b++) wmma::fill_fragment(acc[a][b], 0.f);

    // stage 0 prefetch
    #pragma unroll
    for (int i = tid; i < 512; i += 256) {
        int r = i >> 2, c = (i & 3) * 8;
        cp16(&As[0][r][c], &g_x[(size_t)(i0 + r) * DDIM + c]);
        cp16(&Bs[0][r][c], &g_x[(size_t)(j0 + r) * DDIM + c]);
    }
    CP_COMMIT();

    for (int s = 0; s < 16; s++) {
        int buf = s & 1;
        if (s < 15) {
            int kt = (s + 1) * 32;
            #pragma unroll
            for (int i = tid; i < 512; i += 256) {
                int r = i >> 2, c = (i & 3) * 8;
                cp16(&As[buf ^ 1][r][c], &g_x[(size_t)(i0 + r) * DDIM + kt + c]);
                cp16(&Bs[buf ^ 1][r][c], &g_x[(size_t)(j0 + r) * DDIM + kt + c]);
            }
            CP_COMMIT();
            CP_WAIT1();
        } else {
            CP_WAIT0();
        }
        __syncthreads();
        #pragma unroll
        for (int kc = 0; kc < 2; kc++) {
            wmma::fragment<wmma::matrix_a, 16, 16, 16, __half, wmma::row_major> af[2];
            wmma::fragment<wmma::matrix_b, 16, 16, 16, __half, wmma::col_major> bf[4];
            #pragma unroll
            for (int mi = 0; mi < 2; mi++)
                wmma::load_matrix_sync(af[mi], &As[buf][wm * 32 + mi * 16][kc * 16], 40);
            #pragma unroll
            for (int ni = 0; ni < 4; ni++)
                wmma::load_matrix_sync(bf[ni], &Bs[buf][wn * 64 + ni * 16][kc * 16], 40);
            #pragma unroll
            for (int mi = 0; mi < 2; mi++)
                #pragma unroll
                for (int ni = 0; ni < 4; ni++)
                    wmma::mma_sync(acc[mi][ni], af[mi], bf[ni], acc[mi][ni]);
        }
        __syncthreads();
    }

    // epilogue: patch buffer aliased on Bs (dead now; last loop iter ended in syncthreads)
    float* patch = (float*)Bs + warp * 320;   // 16x20 per warp
    #pragma unroll
    for (int mi = 0; mi < 2; mi++) {
        #pragma unroll
        for (int ni = 0; ni < 4; ni++) {
            wmma::store_matrix_sync(patch, acc[mi][ni], 20, wmma::mem_row_major);
            __syncwarp();
            int rr = lane >> 1;
            int cc0 = (lane & 1) * 8;
            int gi = i0 + wm * 32 + mi * 16 + rr;
            int jbase = wn * 64 + ni * 16 + cc0;
            float si = g_sq[gi];
            __half2* dst = (__half2*)(g_P + (size_t)gi * NPTS + j0 + jbase);
            #pragma unroll
            for (int e = 0; e < 8; e += 2) {
                float g0 = patch[rr * 20 + cc0 + e];
                float g1 = patch[rr * 20 + cc0 + e + 1];
                float d0 = fmaxf(si + sqj[jbase + e]     - 2.f * g0, 0.f);
                float d1 = fmaxf(si + sqj[jbase + e + 1] - 2.f * g1, 0.f);
                dst[e >> 1] = __floats2half2_rn(__expf(-d0 * INV2SIG2), __expf(-d1 * INV2SIG2));
            }
            __syncwarp();
        }
    }
}

// ---------------- K2.5: deterministic row sums over fp16 P ----------------
__global__ void k_rowsum() {
    int row = blockIdx.x;
    const uint4* p = (const uint4*)(g_P + (size_t)row * NPTS);
    float s = 0.f;
    #pragma unroll 4
    for (int i = threadIdx.x; i < 1024; i += 256) {
        uint4 v = p[i];
        __half2* h = (__half2*)&v;
        float2 a = __half22float2(h[0]), b = __half22float2(h[1]);
        float2 c = __half22float2(h[2]), d = __half22float2(h[3]);
        s += (a.x + a.y) + (b.x + b.y) + (c.x + c.y) + (d.x + d.y);
    }
    __shared__ float red[256];
    red[threadIdx.x] = s;
    __syncthreads();
    #pragma unroll
    for (int o = 128; o > 0; o >>= 1) {
        if (threadIdx.x < o) red[threadIdx.x] += red[threadIdx.x + o];
        __syncthreads();
    }
    if (threadIdx.x == 0) g_invr[row] = 1.f / (red[0] + EPSV);
}

// ---------------- K3: O = P @ x (128x128 tile, K=8192, double-buffered) ----------------
__global__ void __launch_bounds__(256) k_pv() {
    __shared__ __half As[2][128][40];
    __shared__ __half Bs[2][32][136];

    int i0 = blockIdx.y * 128;
    int n0 = blockIdx.x * 128;
    int tid = threadIdx.x, warp = tid >> 5;
    int wm = warp >> 1;   // 0..3
    int wn = warp & 1;    // 0..1

    wmma::fragment<wmma::accumulator, 16, 16, 16, float> acc[2][4];
    #pragma unroll
    for (int a = 0; a < 2; a++)
        #pragma unroll
        for (int b = 0; b < 4; b++) wmma::fill_fragment(acc[a][b], 0.f);

    // stage 0 prefetch
    #pragma unroll
    for (int i = tid; i < 512; i += 256) {
        int r = i >> 2, c = (i & 3) * 8;
        cp16(&As[0][r][c], &g_P[(size_t)(i0 + r) * NPTS + c]);
    }
    #pragma unroll
    for (int i = tid; i < 512; i += 256) {
        int r = i >> 4, c = (i & 15) * 8;
        cp16(&Bs[0][r][c], &g_x[(size_t)r * DDIM + n0 + c]);
    }
    CP_COMMIT();

    for (int s = 0; s < 256; s++) {
        int buf = s & 1;
        if (s < 255) {
            int kt = (s + 1) * 32;
            #pragma unroll
            for (int i = tid; i < 512; i += 256) {
                int r = i >> 2, c = (i & 3) * 8;
                cp16(&As[buf ^ 1][r][c], &g_P[(size_t)(i0 + r) * NPTS + kt + c]);
            }
            #pragma unroll
            for (int i = tid; i < 512; i += 256) {
                int r = i >> 4, c = (i & 15) * 8;
                cp16(&Bs[buf ^ 1][r][c], &g_x[(size_t)(kt + r) * DDIM + n0 + c]);
            }
            CP_COMMIT();
            CP_WAIT1();
        } else {
            CP_WAIT0();
        }
        __syncthreads();
        #pragma unroll
        for (int kc = 0; kc < 2; kc++) {
            wmma::fragment<wmma::matrix_a, 16, 16, 16, __half, wmma::row_major> af[2];
            wmma::fragment<wmma::matrix_b, 16, 16, 16, __half, wmma::row_major> bf[4];
            #pragma unroll
            for (int mi = 0; mi < 2; mi++)
                wmma::load_matrix_sync(af[mi], &As[buf][wm * 32 + mi * 16][kc * 16], 40);
            #pragma unroll
            for (int ni = 0; ni < 4; ni++)
                wmma::load_matrix_sync(bf[ni], &Bs[buf][kc * 16][wn * 64 + ni * 16], 136);
            #pragma unroll
            for (int mi = 0; mi < 2; mi++)
                #pragma unroll
                for (int ni = 0; ni < 4; ni++)
                    wmma::mma_sync(acc[mi][ni], af[mi], bf[ni], acc[mi][ni]);
        }
        __syncthreads();
    }

    #pragma unroll
    for (int mi = 0; mi < 2; mi++)
        #pragma unroll
        for (int ni = 0; ni < 4; ni++)
            wmma::store_matrix_sync(
                &g_O[(size_t)(i0 + wm * 32 + mi * 16) * DDIM + n0 + wn * 64 + ni * 16],
                acc[mi][ni], DDIM, wmma::mem_row_major);
}

// ---------------- K4: out = (O * invr) @ W^T + b ----------------
// 128x128 tile, K=512, 8 warps 4(M) x 2(N).
__global__ void __launch_bounds__(256) k_head(const float* __restrict__ bvec,
                                              float* __restrict__ out) {
    __shared__ __half As[128][40];
    __shared__ __half Bs[128][40];
    __shared__ float invs[128], bs[128];

    int i0 = blockIdx.y * 128;
    int n0 = blockIdx.x * 128;
    int tid = threadIdx.x, warp = tid >> 5, lane = tid & 31;
    int wm = warp >> 1;   // 0..3
    int wn = warp & 1;    // 0..1

    if (tid < 128) { invs[tid] = g_invr[i0 + tid]; bs[tid] = bvec[n0 + tid]; }
    __syncthreads();

    wmma::fragment<wmma::accumulator, 16, 16, 16, float> acc[2][4];
    #pragma unroll
    for (int a = 0; a < 2; a++)
        #pragma unroll
        for (int b = 0; b < 4; b++) wmma::fill_fragment(acc[a][b], 0.f);

    for (int kt = 0; kt < DDIM; kt += 32) {
        #pragma unroll
        for (int i = tid; i < 4096; i += 256) {
            int r = i >> 5, c = i & 31;
            As[r][c] = __float2half(g_O[(size_t)(i0 + r) * DDIM + kt + c] * invs[r]);
        }
        #pragma unroll
        for (int i = tid; i < 4096; i += 256) {
            int r = i >> 5, c = i & 31;
            Bs[r][c] = g_W[(size_t)(n0 + r) * DDIM + kt + c];
        }
        __syncthreads();
        #pragma unroll
        for (int kc = 0; kc < 2; kc++) {
            wmma::fragment<wmma::matrix_a, 16, 16, 16, __half, wmma::row_major> af[2];
            wmma::fragment<wmma::matrix_b, 16, 16, 16, __half, wmma::col_major> bf[4];
            #pragma unroll
            for (int mi = 0; mi < 2; mi++)
                wmma::load_matrix_sync(af[mi], &As[wm * 32 + mi * 16][kc * 16], 40);
            #pragma unroll
            for (int ni = 0; ni < 4; ni++)
                wmma::load_matrix_sync(bf[ni], &Bs[wn * 64 + ni * 16][kc * 16], 40);
            #pragma unroll
            for (int mi = 0; mi < 2; mi++)
                #pragma unroll
                for (int ni = 0; ni < 4; ni++)
                    wmma::mma_sync(acc[mi][ni], af[mi], bf[ni], acc[mi][ni]);
        }
        __syncthreads();
    }

    // epilogue: patch aliased on As
    float* patch = (float*)As + warp * 320;
    #pragma unroll
    for (int mi = 0; mi < 2; mi++) {
        #pragma unroll
        for (int ni = 0; ni < 4; ni++) {
            wmma::store_matrix_sync(patch, acc[mi][ni], 20, wmma::mem_row_major);
            __syncwarp();
            int rr = lane >> 1;
            int cc0 = (lane & 1) * 8;
            int gi = i0 + wm * 32 + mi * 16 + rr;
            int nb = wn * 64 + ni * 16 + cc0;
            #pragma unroll
            for (int e = 0; e < 8; e++)
                out[(size_t)gi * ODIM + n0 + nb + e] = patch[rr * 20 + cc0 + e] + bs[nb + e];
            __syncwarp();
        }
    }
}

// ---------------- launch ----------------
extern "C" void kernel_launch(void* const* d_in, const int* in_sizes, int n_in,
                              void* d_out, int out_size) {
    const float* x = (const float*)d_in[0];
    const float* W = (const float*)d_in[1];
    const float* b = (const float*)d_in[2];
    float* out = (float*)d_out;

    k_prep_x<<<NPTS / 8, 256>>>(x);
    k_prep_w<<<(ODIM * DDIM / 4) / 256, 256>>>(W);
    k_gauss<<<dim3(NPTS / 128, NPTS / 128), 256>>>();
    k_rowsum<<<NPTS, 256>>>();
    k_pv<<<dim3(DDIM / 128, NPTS / 128), 256>>>();
    k_head<<<dim3(ODIM / 128, NPTS / 128), 256>>>(b, out);
}

// round 6
// speedup vs baseline: 7.6159x; 1.2573x over previous
#include <cuda_runtime.h>
#include <cuda_fp16.h>
#include <mma.h>
#include <cstdint>

using namespace nvcuda;

#define NPTS 8192
#define DDIM 512
#define ODIM 512

static constexpr float INV2SIG2 = 1.0f / 2048.0f;   // 1/(2*32*32)
static constexpr float EPSV = 1e-8f;

// ---------------- scratch ----------------
__device__ __half g_x[(size_t)NPTS * DDIM];      // fp16 x [N][D]
__device__ __half g_W[(size_t)ODIM * DDIM];      // fp16 W [O][D]
__device__ __half g_P[(size_t)NPTS * NPTS];      // fp16 weights, 128 MB
__device__ __half g_Y[(size_t)NPTS * DDIM];      // fp16 normalized P@x
__device__ float  g_sq[NPTS];
__device__ float  g_invr[NPTS];
__device__ float  g_part[(size_t)64 * NPTS];     // per-jtile row partial sums (2 MB)

// ---------------- cp.async ----------------
__device__ __forceinline__ void cp16s(unsigned dst, const void* src) {
    asm volatile("cp.async.cg.shared.global [%0], [%1], 16;" :: "r"(dst), "l"(src));
}
#define CP_COMMIT() asm volatile("cp.async.commit_group;" ::: "memory")
#define CP_WAIT1()  asm volatile("cp.async.wait_group 1;" ::: "memory")
#define CP_WAIT0()  asm volatile("cp.async.wait_group 0;" ::: "memory")

__device__ __forceinline__ unsigned smem_u32(const void* p) {
    return (unsigned)__cvta_generic_to_shared(p);
}

// stage geometry: BK=64. A tile 128r x 72 halves (144B row), B same footprint.
// STAGE = 36864 B (A 18432 + B 18432). Two stages = 72 KB dynamic.
#define A_ROW_H   72
#define A_BYTES   18432
#define STAGE_B   36864
#define DYN_SMEM  (2 * STAGE_B)

// pv B tile: 64 k-rows x 136 halves (272 B row) = 17408 B, fits in B slot.
#define PVB_ROW_H 136

// ---------------- prep kernels ----------------
__global__ void k_prep_x(const float* __restrict__ x) {
    int row = blockIdx.x * 8 + (threadIdx.x >> 5);
    int lane = threadIdx.x & 31;
    const float4* xr = (const float4*)(x + (size_t)row * DDIM);
    float s = 0.f;
    #pragma unroll
    for (int i = lane; i < 128; i += 32) {
        float4 v = xr[i];
        s += v.x * v.x + v.y * v.y + v.z * v.z + v.w * v.w;
        __half2* dst = (__half2*)(g_x + (size_t)row * DDIM + i * 4);
        dst[0] = __floats2half2_rn(v.x, v.y);
        dst[1] = __floats2half2_rn(v.z, v.w);
    }
    #pragma unroll
    for (int o = 16; o > 0; o >>= 1) s += __shfl_xor_sync(0xffffffff, s, o);
    if (lane == 0) g_sq[row] = s;
}

__global__ void k_prep_w(const float* __restrict__ W) {
    int i = blockIdx.x * blockDim.x + threadIdx.x;
    float4 v = ((const float4*)W)[i];
    __half2* dst = (__half2*)(g_W + (size_t)i * 4);
    dst[0] = __floats2half2_rn(v.x, v.y);
    dst[1] = __floats2half2_rn(v.z, v.w);
}

// ---------------- K2: Gram 128x128 -> exp -> P fp16 + fused row partials ----------------
// 256 thr, 8 warps 4(M)x2(N), warp tile 32x64, BK=64 (8 K-iters), double-buffered.
__global__ void __launch_bounds__(256) k_gauss() {
    extern __shared__ __align__(16) char dyn[];
    __shared__ float sqj[128];
    __shared__ float part2[2][128];

    unsigned sb = smem_u32(dyn);
    __half* Hs = (__half*)dyn;

    int i0 = blockIdx.y * 128;
    int j0 = blockIdx.x * 128;
    int tid = threadIdx.x, warp = tid >> 5, lane = tid & 31;
    int wm = warp >> 1;   // 0..3
    int wn = warp & 1;    // 0..1

    if (tid < 128) sqj[tid] = g_sq[j0 + tid];

    wmma::fragment<wmma::accumulator, 16, 16, 16, float> acc[2][4];
    #pragma unroll
    for (int a = 0; a < 2; a++)
        #pragma unroll
        for (int b = 0; b < 4; b++) wmma::fill_fragment(acc[a][b], 0.f);

    auto load_chunk = [&](int c, int st) {
        unsigned ab = sb + st * STAGE_B;
        unsigned bb = ab + A_BYTES;
        const __half* ga = g_x + (size_t)i0 * DDIM + c * 64;
        const __half* gb = g_x + (size_t)j0 * DDIM + c * 64;
        #pragma unroll
        for (int q = 0; q < 4; q++) {      // 1024 granules A
            int idx = tid + q * 256;
            int r = idx >> 3, g = idx & 7;
            cp16s(ab + r * 144 + g * 16, ga + (size_t)r * DDIM + g * 8);
        }
        #pragma unroll
        for (int q = 0; q < 4; q++) {      // 1024 granules B
            int idx = tid + q * 256;
            int r = idx >> 3, g = idx & 7;
            cp16s(bb + r * 144 + g * 16, gb + (size_t)r * DDIM + g * 8);
        }
        CP_COMMIT();
    };

    load_chunk(0, 0);
    for (int s = 0; s < 8; s++) {
        int buf = s & 1;
        if (s < 7) { load_chunk(s + 1, buf ^ 1); CP_WAIT1(); } else { CP_WAIT0(); }
        __syncthreads();
        __half* A = Hs + buf * (STAGE_B / 2);
        __half* B = A + A_BYTES / 2;
        #pragma unroll
        for (int kc = 0; kc < 4; kc++) {
            wmma::fragment<wmma::matrix_a, 16, 16, 16, __half, wmma::row_major> af[2];
            #pragma unroll
            for (int mi = 0; mi < 2; mi++)
                wmma::load_matrix_sync(af[mi], A + (wm * 32 + mi * 16) * A_ROW_H + kc * 16, A_ROW_H);
            #pragma unroll
            for (int ni = 0; ni < 4; ni++) {
                wmma::fragment<wmma::matrix_b, 16, 16, 16, __half, wmma::col_major> bf;
                wmma::load_matrix_sync(bf, B + (wn * 64 + ni * 16) * A_ROW_H + kc * 16, A_ROW_H);
                wmma::mma_sync(acc[0][ni], af[0], bf, acc[0][ni]);
                wmma::mma_sync(acc[1][ni], af[1], bf, acc[1][ni]);
            }
        }
        __syncthreads();
    }

    // epilogue: patch aliased on dyn (free after trailing sync)
    float* patch = (float*)dyn + warp * 320;   // 16x20
    int rr = lane >> 1;
    int cc0 = (lane & 1) * 8;
    #pragma unroll
    for (int mi = 0; mi < 2; mi++) {
        int gi = i0 + wm * 32 + mi * 16 + rr;
        float si = g_sq[gi];
        float s = 0.f;
        #pragma unroll
        for (int ni = 0; ni < 4; ni++) {
            wmma::store_matrix_sync(patch, acc[mi][ni], 20, wmma::mem_row_major);
            __syncwarp();
            int jl = wn * 64 + ni * 16 + cc0;
            __half2 buf2[4];
            #pragma unroll
            for (int e = 0; e < 8; e += 2) {
                float d0 = fmaxf(si + sqj[jl + e]     - 2.f * patch[rr * 20 + cc0 + e],     0.f);
                float d1 = fmaxf(si + sqj[jl + e + 1] - 2.f * patch[rr * 20 + cc0 + e + 1], 0.f);
                __half2 hp = __floats2half2_rn(__expf(-d0 * INV2SIG2), __expf(-d1 * INV2SIG2));
                buf2[e >> 1] = hp;
                float2 hf = __half22float2(hp);
                s += hf.x + hf.y;
            }
            *(uint4*)(g_P + (size_t)gi * NPTS + j0 + jl) = *(const uint4*)buf2;
            __syncwarp();
        }
        s += __shfl_xor_sync(0xffffffff, s, 1);
        if ((lane & 1) == 0) part2[wn][wm * 32 + mi * 16 + rr] = s;
    }
    __syncthreads();
    if (tid < 128) g_part[(size_t)blockIdx.x * NPTS + i0 + tid] = part2[0][tid] + part2[1][tid];
}

// ---------------- K2.5: reduce 64 partials/row -> 1/(sum+eps) ----------------
__global__ void k_rowsum() {
    int row = blockIdx.x * 256 + threadIdx.x;
    float s = 0.f;
    #pragma unroll
    for (int jt = 0; jt < 64; jt++) s += g_part[(size_t)jt * NPTS + row];
    g_invr[row] = 1.f / (s + EPSV);
}

// ---------------- K3: Y = (P @ x) * invr, fp16 out. 128x128 tile, K=8192 ----------------
__global__ void __launch_bounds__(256) k_pv() {
    extern __shared__ __align__(16) char dyn[];
    unsigned sb = smem_u32(dyn);
    __half* Hs = (__half*)dyn;

    int i0 = blockIdx.y * 128;
    int n0 = blockIdx.x * 128;
    int tid = threadIdx.x, warp = tid >> 5, lane = tid & 31;
    int wm = warp >> 1;   // 0..3
    int wn = warp & 1;    // 0..1

    wmma::fragment<wmma::accumulator, 16, 16, 16, float> acc[2][4];
    #pragma unroll
    for (int a = 0; a < 2; a++)
        #pragma unroll
        for (int b = 0; b < 4; b++) wmma::fill_fragment(acc[a][b], 0.f);

    auto load_chunk = [&](int c, int st) {
        unsigned ab = sb + st * STAGE_B;
        unsigned bb = ab + A_BYTES;
        const __half* ga = g_P + (size_t)i0 * NPTS + c * 64;
        const __half* gb = g_x + (size_t)(c * 64) * DDIM + n0;
        #pragma unroll
        for (int q = 0; q < 4; q++) {      // A: 128r x 8 granules
            int idx = tid + q * 256;
            int r = idx >> 3, g = idx & 7;
            cp16s(ab + r * 144 + g * 16, ga + (size_t)r * NPTS + g * 8);
        }
        #pragma unroll
        for (int q = 0; q < 4; q++) {      // B: 64r x 16 granules
            int idx = tid + q * 256;
            int r = idx >> 4, g = idx & 15;
            cp16s(bb + r * 272 + g * 16, gb + (size_t)r * DDIM + g * 8);
        }
        CP_COMMIT();
    };

    load_chunk(0, 0);
    for (int s = 0; s < 128; s++) {
        int buf = s & 1;
        if (s < 127) { load_chunk(s + 1, buf ^ 1); CP_WAIT1(); } else { CP_WAIT0(); }
        __syncthreads();
        __half* A = Hs + buf * (STAGE_B / 2);
        __half* B = A + A_BYTES / 2;
        #pragma unroll
        for (int kc = 0; kc < 4; kc++) {
            wmma::fragment<wmma::matrix_a, 16, 16, 16, __half, wmma::row_major> af[2];
            #pragma unroll
            for (int mi = 0; mi < 2; mi++)
                wmma::load_matrix_sync(af[mi], A + (wm * 32 + mi * 16) * A_ROW_H + kc * 16, A_ROW_H);
            #pragma unroll
            for (int ni = 0; ni < 4; ni++) {
                wmma::fragment<wmma::matrix_b, 16, 16, 16, __half, wmma::row_major> bf;
                wmma::load_matrix_sync(bf, B + (kc * 16) * PVB_ROW_H + wn * 64 + ni * 16, PVB_ROW_H);
                wmma::mma_sync(acc[0][ni], af[0], bf, acc[0][ni]);
                wmma::mma_sync(acc[1][ni], af[1], bf, acc[1][ni]);
            }
        }
        __syncthreads();
    }

    float* patch = (float*)dyn + warp * 320;
    int rr = lane >> 1;
    int cc0 = (lane & 1) * 8;
    #pragma unroll
    for (int mi = 0; mi < 2; mi++) {
        int gi = i0 + wm * 32 + mi * 16 + rr;
        float inv = g_invr[gi];
        #pragma unroll
        for (int ni = 0; ni < 4; ni++) {
            wmma::store_matrix_sync(patch, acc[mi][ni], 20, wmma::mem_row_major);
            __syncwarp();
            int nl = wn * 64 + ni * 16 + cc0;
            __half2 buf2[4];
            #pragma unroll
            for (int e = 0; e < 8; e += 2)
                buf2[e >> 1] = __floats2half2_rn(patch[rr * 20 + cc0 + e] * inv,
                                                 patch[rr * 20 + cc0 + e + 1] * inv);
            *(uint4*)(g_Y + (size_t)gi * DDIM + n0 + nl) = *(const uint4*)buf2;
            __syncwarp();
        }
    }
}

// ---------------- K4: out = Y @ W^T + b, fp32 out. 128x128 tile, K=512 ----------------
__global__ void __launch_bounds__(256) k_head(const float* __restrict__ bvec,
                                              float* __restrict__ out) {
    extern __shared__ __align__(16) char dyn[];
    __shared__ float bs[128];
    unsigned sb = smem_u32(dyn);
    __half* Hs = (__half*)dyn;

    int i0 = blockIdx.y * 128;
    int n0 = blockIdx.x * 128;
    int tid = threadIdx.x, warp = tid >> 5, lane = tid & 31;
    int wm = warp >> 1;
    int wn = warp & 1;

    if (tid < 128) bs[tid] = bvec[n0 + tid];

    wmma::fragment<wmma::accumulator, 16, 16, 16, float> acc[2][4];
    #pragma unroll
    for (int a = 0; a < 2; a++)
        #pragma unroll
        for (int b = 0; b < 4; b++) wmma::fill_fragment(acc[a][b], 0.f);

    auto load_chunk = [&](int c, int st) {
        unsigned ab = sb + st * STAGE_B;
        unsigned bb = ab + A_BYTES;
        const __half* ga = g_Y + (size_t)i0 * DDIM + c * 64;
        const __half* gb = g_W + (size_t)n0 * DDIM + c * 64;
        #pragma unroll
        for (int q = 0; q < 4; q++) {
            int idx = tid + q * 256;
            int r = idx >> 3, g = idx & 7;
            cp16s(ab + r * 144 + g * 16, ga + (size_t)r * DDIM + g * 8);
        }
        #pragma unroll
        for (int q = 0; q < 4; q++) {
            int idx = tid + q * 256;
            int r = idx >> 3, g = idx & 7;
            cp16s(bb + r * 144 + g * 16, gb + (size_t)r * DDIM + g * 8);
        }
        CP_COMMIT();
    };

    load_chunk(0, 0);
    for (int s = 0; s < 8; s++) {
        int buf = s & 1;
        if (s < 7) { load_chunk(s + 1, buf ^ 1); CP_WAIT1(); } else { CP_WAIT0(); }
        __syncthreads();
        __half* A = Hs + buf * (STAGE_B / 2);
        __half* B = A + A_BYTES / 2;
        #pragma unroll
        for (int kc = 0; kc < 4; kc++) {
            wmma::fragment<wmma::matrix_a, 16, 16, 16, __half, wmma::row_major> af[2];
            #pragma unroll
            for (int mi = 0; mi < 2; mi++)
                wmma::load_matrix_sync(af[mi], A + (wm * 32 + mi * 16) * A_ROW_H + kc * 16, A_ROW_H);
            #pragma unroll
            for (int ni = 0; ni < 4; ni++) {
                wmma::fragment<wmma::matrix_b, 16, 16, 16, __half, wmma::col_major> bf;
                wmma::load_matrix_sync(bf, B + (wn * 64 + ni * 16) * A_ROW_H + kc * 16, A_ROW_H);
                wmma::mma_sync(acc[0][ni], af[0], bf, acc[0][ni]);
                wmma::mma_sync(acc[1][ni], af[1], bf, acc[1][ni]);
            }
        }
        __syncthreads();
    }

    float* patch = (float*)dyn + warp * 320;
    int rr = lane >> 1;
    int cc0 = (lane & 1) * 8;
    #pragma unroll
    for (int mi = 0; mi < 2; mi++) {
        int gi = i0 + wm * 32 + mi * 16 + rr;
        #pragma unroll
        for (int ni = 0; ni < 4; ni++) {
            wmma::store_matrix_sync(patch, acc[mi][ni], 20, wmma::mem_row_major);
            __syncwarp();
            int nl = wn * 64 + ni * 16 + cc0;
            float* dst = out + (size_t)gi * ODIM + n0 + nl;
            #pragma unroll
            for (int e = 0; e < 8; e++)
                dst[e] = patch[rr * 20 + cc0 + e] + bs[nl + e];
            __syncwarp();
        }
    }
}

// ---------------- launch ----------------
extern "C" void kernel_launch(void* const* d_in, const int* in_sizes, int n_in,
                              void* d_out, int out_size) {
    const float* x = (const float*)d_in[0];
    const float* W = (const float*)d_in[1];
    const float* b = (const float*)d_in[2];
    float* out = (float*)d_out;

    static bool attr_done = false;
    if (!attr_done) {
        cudaFuncSetAttribute(k_gauss, cudaFuncAttributeMaxDynamicSharedMemorySize, DYN_SMEM);
        cudaFuncSetAttribute(k_pv,    cudaFuncAttributeMaxDynamicSharedMemorySize, DYN_SMEM);
        cudaFuncSetAttribute(k_head,  cudaFuncAttributeMaxDynamicSharedMemorySize, DYN_SMEM);
        attr_done = true;
    }

    k_prep_x<<<NPTS / 8, 256>>>(x);
    k_prep_w<<<(ODIM * DDIM / 4) / 256, 256>>>(W);
    k_gauss<<<dim3(NPTS / 128, NPTS / 128), 256, DYN_SMEM>>>();
    k_rowsum<<<NPTS / 256, 256>>>();
    k_pv<<<dim3(DDIM / 128, NPTS / 128), 256, DYN_SMEM>>>();
    k_head<<<dim3(ODIM / 128, NPTS / 128), 256, DYN_SMEM>>>(b, out);
}